// round 10
// baseline (speedup 1.0000x reference)
#include <cuda_runtime.h>

#define W 512
#define H 512
#define NPLANES 96
#define SKEW 3
#define NWARPS 16            // one band (32 rows) per warp, whole plane per block
#define CH 16                // columns per sync chunk
#define LAG 96               // 32 rows * SKEW: producer lead needed by consumer
#define NSTEP_PAD 608        // ceil((512 + 3*31)=605) to multiple of CH
#define NCHUNK (NSTEP_PAD / CH)

// Floyd-Steinberg 1-bit error diffusion — byte-exact R3 structure (best: 260us)
// with ONE change: the inter-warp spin is clock-paced. R3's raw spin issues an
// LDS poll every ~30 cyc from ~12 waiting warps, stealing a large share of the
// LSU/MIO accept rate from the active warps' LDG/LDS/STG/SHFL (the suspected
// source of the ~4x gap between modeled and measured step cost). Pacing the
// poll with a ~40-cyc CS2R busy-wait removes the LSU traffic with bounded
// (+~70 cyc/link) wake latency — unlike nanosleep (R4, us quantization) or
// mbarrier sleep (R5) or bulk-sync (R8), which all regressed.
__global__ void __launch_bounds__(NWARPS * 32, 1)
fs_dither_kernel(const float* __restrict__ x, float* __restrict__ out) {
    __shared__ float errbuf[NWARPS][W];
    __shared__ float zbuf[W];
    __shared__ volatile unsigned progress[NWARPS];

    const int tid = threadIdx.x;
    const int w = tid >> 5;
    const int lane = tid & 31;
    const int plane = blockIdx.x;

    const float* __restrict__ xp = x + (size_t)plane * (H * W);
    float* __restrict__ op = out + (size_t)plane * (H * W);

    for (int i = tid; i < W; i += NWARPS * 32) zbuf[i] = 0.0f;
    if (tid < NWARPS) progress[tid] = 0u;
    __syncthreads();

    const float* __restrict__ prevrow = (w == 0) ? zbuf : errbuf[w - 1];
    float* __restrict__ myrow = errbuf[w];

    const int row = w * 32 + lane;
    const float* __restrict__ xrow = xp + (size_t)row * W;
    float* __restrict__ orow = op + (size_t)row * W;

    // Delay line: at step t lane l consumes e_ur=r2, e_u=r3, e_ul=r4 (row-above
    // errs at cols c+1, c, c-1); r1 is the 3-ahead value (lane0: prevrow[t+3]).
    float r1 = 0.0f, r2 = 0.0f, r3 = 0.0f, r4 = 0.0f;
    float left = 0.0f;

    int t = 0;
    for (int k = 0; k < NCHUNK; ++k) {
        if (w != 0) {
            unsigned need = (unsigned)(t + CH + LAG);
            if (need > NSTEP_PAD) need = NSTEP_PAD;
            if (progress[w - 1] < need) {
                // Clock-paced spin: one SMEM poll per ~40-cyc CS2R window.
                // Keeps waiting warps off the LSU/MIO pipes that the active
                // warps' memory ops need, with bounded wake latency.
                do {
                    unsigned s0 = (unsigned)clock();
                    while ((unsigned)clock() - s0 < 40u) { }
                } while (progress[w - 1] < need);
            }
        }
        __syncwarp();
        __threadfence_block();   // acquire: producer's STS now visible

        if (k == 0 && lane == 0) {
            // prev[-1]=0 (pad), prev[0..2]; gated by the first poll (need>=112)
            r4 = 0.0f;
            r3 = prevrow[0];
            r2 = prevrow[1];
            r1 = prevrow[2];
        }

        #pragma unroll 4
        for (int i = 0; i < CH; ++i, ++t) {
            const int c = t - SKEW * lane;
            const bool active = ((unsigned)c < (unsigned)W);
            const float e_ur = r2, e_u = r3, e_ul = r4;

            // Clamped-address load keeps inactive lanes branch-free (L1-hit).
            int cl = c < 0 ? 0 : (c > W - 1 ? W - 1 : c);
            float xv = __ldg(xrow + cl);

            // x = clip(x,-1,1); x01 = (x+1)/2  (exact, matches reference)
            xv = fminf(fmaxf(xv, -1.0f), 1.0f);
            float x01 = __fmul_rn(__fadd_rn(xv, 1.0f), 0.5f);

            // up = (1/16*e_ul + 5/16*e_u) + 3/16*e_ur  (reference order, no FMA)
            float u = __fadd_rn(__fadd_rn(__fmul_rn(0.0625f, e_ul),
                                          __fmul_rn(0.3125f, e_u)),
                                __fmul_rn(0.1875f, e_ur));
            float pre = __fadd_rn(x01, u);
            float raw = __fadd_rn(pre, __fmul_rn(0.4375f, left));
            float val = fminf(fmaxf(raw, 0.0f), 1.0f);

            // q = round-half-even(val), val in [0,1]  <=>  raw > 0.5.
            // d = 0.5 - raw has exact sign (Sterbenz in [0.25,1]); tie -> q=0.
            float d = __fadd_rn(0.5f, -raw);
            unsigned s = (unsigned)(__float_as_int(d) >> 31);
            // err = val - q exactly: val + (-1.0f masked); Sterbenz-exact.
            float err = __fadd_rn(val, __uint_as_float(s & 0xBF800000u));
            err = active ? err : 0.0f;   // inactive lanes feed zero padding

            if (active) {
                // output = 2*q - 1 in {-1,+1}
                orow[c] = __uint_as_float(0xBF800000u ^ (s & 0x80000000u));
                if (lane == 31) myrow[c] = err;   // hand off to next band
            }
            left = err;

            // Cross-lane propagation (2 steps of slack before consumption).
            float sh = __shfl_up_sync(0xFFFFFFFFu, err, 1);
            const int pi = t + SKEW;
            float pv = (pi < W) ? prevrow[pi] : 0.0f;  // broadcast LDS
            if (lane == 0) sh = pv;                    // SEL, no branch
            r4 = r3; r3 = r2; r2 = r1; r1 = sh;
        }

        if (lane == 31) {
            __threadfence_block();     // release: STS before counter
            progress[w] = (unsigned)t;
        }
    }
}

extern "C" void kernel_launch(void* const* d_in, const int* in_sizes, int n_in,
                              void* d_out, int out_size) {
    (void)in_sizes; (void)n_in; (void)out_size;
    const float* x = (const float*)d_in[0];
    float* out = (float*)d_out;
    fs_dither_kernel<<<NPLANES, NWARPS * 32>>>(x, out);
}

// round 11
// speedup vs baseline: 1.0221x; 1.0221x over previous
#include <cuda_runtime.h>
#include <cstdint>

#define W 512
#define H 512
#define NPLANES 96
#define SKEW 3
#define NWARPS 16            // one band (32 rows) per warp, whole plane per block
#define CH 16                // columns per sync chunk
#define NSTEP_PAD 608        // ceil((512 + 3*31)=605) to multiple of CH
#define NCHUNK (NSTEP_PAD / CH)   // 38
#define NLINK (NWARPS - 1)        // 15 band links

__device__ __forceinline__ uint32_t smem_u32(const void* p) {
    return (uint32_t)__cvta_generic_to_shared(p);
}
__device__ __forceinline__ void mbar_init(uint32_t a, uint32_t cnt) {
    asm volatile("mbarrier.init.shared.b64 [%0], %1;" :: "r"(a), "r"(cnt) : "memory");
}
// Release-arrive (PTX default arrive has release semantics at cta scope).
__device__ __forceinline__ void mbar_arrive(uint32_t a) {
    asm volatile("mbarrier.arrive.release.cta.shared::cta.b64 _, [%0];"
                 :: "r"(a) : "memory");
}
// Wait for phase-0 completion of a single-use barrier. HW-sleep (no issue
// while suspended), wakeup-after-arrive ~60 cyc.
__device__ __forceinline__ void mbar_wait0(uint32_t a) {
    uint32_t done;
    asm volatile(
        "{\n\t.reg .pred p;\n\t"
        "mbarrier.try_wait.parity.acquire.cta.shared::cta.b64 p, [%1], 0;\n\t"
        "selp.b32 %0, 1, 0, p;\n\t}"
        : "=r"(done) : "r"(a) : "memory");
    while (!done) {
        asm volatile(
            "{\n\t.reg .pred p;\n\t"
            "mbarrier.try_wait.parity.acquire.cta.shared::cta.b64 p, [%1], 0, 0x989680;\n\t"
            "selp.b32 %0, 1, 0, p;\n\t}"
            : "=r"(done) : "r"(a) : "memory");
    }
}

// Floyd-Steinberg 1-bit error diffusion — R3 structure and inner loop BYTE
// EXACT (best: 260us); the ONLY change is the inter-warp wait: per-(link,chunk)
// single-use mbarriers replace the volatile spin. Rationale (R4/R10 evidence):
// the B300 arbiter is hi-wid-first and the spinners are the high-wid warps, so
// raw-spin polls preferentially steal issue slots from the ~5 computing warps;
// clock-paced spin issues MORE (CS2R loop), nanosleep wakes ~1us too late per
// cascade link. mbarrier try_wait is a HW-sleep with ~60-cyc wake: zero issue
// theft, negligible wake cost (~60 x 143 rounds ~ 5us bound).
__global__ void __launch_bounds__(NWARPS * 32, 1)
fs_dither_kernel(const float* __restrict__ x, float* __restrict__ out) {
    __shared__ float errbuf[NWARPS][W];
    __shared__ float zbuf[W];
    __shared__ uint64_t mbar[NLINK][NCHUNK];

    const int tid = threadIdx.x;
    const int w = tid >> 5;
    const int lane = tid & 31;
    const int plane = blockIdx.x;

    const float* __restrict__ xp = x + (size_t)plane * (H * W);
    float* __restrict__ op = out + (size_t)plane * (H * W);

    for (int i = tid; i < W; i += NWARPS * 32) zbuf[i] = 0.0f;
    if (tid == 0) {
        uint32_t base = smem_u32(&mbar[0][0]);
        for (int i = 0; i < NLINK * NCHUNK; ++i) mbar_init(base + 8u * i, 1u);
    }
    __syncthreads();

    const float* __restrict__ prevrow = (w == 0) ? zbuf : errbuf[w - 1];
    float* __restrict__ myrow = errbuf[w];

    const int row = w * 32 + lane;
    const float* __restrict__ xrow = xp + (size_t)row * W;
    float* __restrict__ orow = op + (size_t)row * W;

    // Delay line: at step t lane l consumes e_ur=r2, e_u=r3, e_ul=r4 (row-above
    // errs at cols c+1, c, c-1); r1 is the 3-ahead value (lane0: prevrow[t+3]).
    float r1 = 0.0f, r2 = 0.0f, r3 = 0.0f, r4 = 0.0f;
    float left = 0.0f;

    int t = 0;
    for (int k = 0; k < NCHUNK; ++k) {
        if (w != 0) {
            // Consumer chunk k needs producer progress >= (k+1)*16 + 96, i.e.
            // producer chunk j = k+6 complete (clamped to the last chunk).
            int j = k + 6; if (j > NCHUNK - 1) j = NCHUNK - 1;
            mbar_wait0(smem_u32(&mbar[w - 1][j]));   // acquire; HW-sleep
        }
        __syncwarp();

        if (k == 0 && lane == 0) {
            // prev[-1]=0 (pad), prev[0..2]; producer chunk 6 (cols<=111) done.
            r4 = 0.0f;
            r3 = prevrow[0];
            r2 = prevrow[1];
            r1 = prevrow[2];
        }

        #pragma unroll 4
        for (int i = 0; i < CH; ++i, ++t) {
            const int c = t - SKEW * lane;
            const bool active = ((unsigned)c < (unsigned)W);
            const float e_ur = r2, e_u = r3, e_ul = r4;

            // Clamped-address load keeps inactive lanes branch-free (L1-hit).
            int cl = c < 0 ? 0 : (c > W - 1 ? W - 1 : c);
            float xv = __ldg(xrow + cl);

            // x = clip(x,-1,1); x01 = (x+1)/2  (exact, matches reference)
            xv = fminf(fmaxf(xv, -1.0f), 1.0f);
            float x01 = __fmul_rn(__fadd_rn(xv, 1.0f), 0.5f);

            // up = (1/16*e_ul + 5/16*e_u) + 3/16*e_ur  (reference order, no FMA)
            float u = __fadd_rn(__fadd_rn(__fmul_rn(0.0625f, e_ul),
                                          __fmul_rn(0.3125f, e_u)),
                                __fmul_rn(0.1875f, e_ur));
            float pre = __fadd_rn(x01, u);
            float raw = __fadd_rn(pre, __fmul_rn(0.4375f, left));
            float val = fminf(fmaxf(raw, 0.0f), 1.0f);

            // q = round-half-even(val), val in [0,1]  <=>  raw > 0.5.
            // d = 0.5 - raw has exact sign (Sterbenz in [0.25,1]); tie -> q=0.
            float d = __fadd_rn(0.5f, -raw);
            unsigned s = (unsigned)(__float_as_int(d) >> 31);
            // err = val - q exactly: val + (-1.0f masked); Sterbenz-exact.
            float err = __fadd_rn(val, __uint_as_float(s & 0xBF800000u));
            err = active ? err : 0.0f;   // inactive lanes feed zero padding

            if (active) {
                // output = 2*q - 1 in {-1,+1}
                orow[c] = __uint_as_float(0xBF800000u ^ (s & 0x80000000u));
                if (lane == 31) myrow[c] = err;   // hand off to next band
            }
            left = err;

            // Cross-lane propagation (2 steps of slack before consumption).
            float sh = __shfl_up_sync(0xFFFFFFFFu, err, 1);
            const int pi = t + SKEW;
            float pv = (pi < W) ? prevrow[pi] : 0.0f;  // broadcast LDS
            if (lane == 0) sh = pv;                    // SEL, no branch
            r4 = r3; r3 = r2; r2 = r1; r1 = sh;
        }

        // Producer: publish chunk k. lane 31's release-arrive orders its STS
        // of this chunk before the consumer's acquire (single-writer row).
        if (w != NWARPS - 1 && lane == 31)
            mbar_arrive(smem_u32(&mbar[w][k]));
    }
}

extern "C" void kernel_launch(void* const* d_in, const int* in_sizes, int n_in,
                              void* d_out, int out_size) {
    (void)in_sizes; (void)n_in; (void)out_size;
    const float* x = (const float*)d_in[0];
    float* out = (float*)d_out;
    fs_dither_kernel<<<NPLANES, NWARPS * 32>>>(x, out);
}